// round 8
// baseline (speedup 1.0000x reference)
#include <cuda_runtime.h>
#include <cuda_bf16.h>
#include <math.h>
#include <stdint.h>

#define BSZ  4096
#define KSEL 200

// ---- scratch (__device__ globals; no allocations allowed) ----
__device__ float g_S[(size_t)BSZ * BSZ];          // 64 MB similarity matrix
__device__ __nv_bfloat16 g_Fhi[(size_t)BSZ * 128];
__device__ __nv_bfloat16 g_Flo[(size_t)BSZ * 128];
__device__ float g_perrow[BSZ];
__device__ float g_validf[BSZ];

// tcgen05 only exists on the arch-specific target; gate ALL inline PTX on it.
#if defined(__CUDA_ARCH_FEAT_SM103_ALL) || defined(__CUDA_ARCH_FEAT_SM100_ALL)
#define HAS_TCGEN05 1
#else
#define HAS_TCGEN05 0
#endif

#if HAS_TCGEN05
// ===========================================================================
// PTX helpers (compiled only when the target supports tcgen05)
// ===========================================================================
__device__ __forceinline__ uint32_t smem_u32(const void* p) {
    uint32_t a;
    asm("{ .reg .u64 t; cvta.to.shared.u64 t, %1; cvt.u32.u64 %0, t; }" : "=r"(a) : "l"(p));
    return a;
}
__device__ __forceinline__ uint32_t elect_one_pred() {
    uint32_t pred;
    asm volatile("{\n\t.reg .pred p;\n\telect.sync _|p, 0xFFFFFFFF;\n\t"
                 "selp.b32 %0, 1, 0, p;\n\t}" : "=r"(pred));
    return pred;
}
#define TCGEN05_ALLOC(smem_addr, nCols) \
    asm volatile("tcgen05.alloc.cta_group::1.sync.aligned.shared::cta.b32 [%0], %1;" \
                 :: "r"((uint32_t)(smem_addr)), "r"((uint32_t)(nCols)) : "memory")
#define TCGEN05_RELINQUISH() \
    asm volatile("tcgen05.relinquish_alloc_permit.cta_group::1.sync.aligned;")
#define TCGEN05_DEALLOC(tmem_addr, nCols) \
    asm volatile("tcgen05.dealloc.cta_group::1.sync.aligned.b32 %0, %1;" \
                 :: "r"(tmem_addr), "r"((uint32_t)(nCols)))
#define TCGEN05_COMMIT(mbar) \
    asm volatile("tcgen05.commit.cta_group::1.mbarrier::arrive::one.shared::cluster.b64 [%0];" \
                 :: "r"((uint32_t)(mbar)) : "memory")
#define TCGEN05_WAIT_LD()  asm volatile("tcgen05.wait::ld.sync.aligned;" ::: "memory")
#define TCGEN05_FENCE_BEFORE() asm volatile("tcgen05.fence::before_thread_sync;" ::: "memory")
#define TCGEN05_FENCE_AFTER()  asm volatile("tcgen05.fence::after_thread_sync;" ::: "memory")
#define MBARRIER_INIT(mbar, cnt) \
    asm volatile("mbarrier.init.shared.b64 [%0], %1;" :: "r"((uint32_t)(mbar)), "r"((uint32_t)(cnt)) : "memory")
#define MBARRIER_WAIT_PARITY(mbar, par) do { \
    uint32_t _m = (uint32_t)(mbar); uint32_t _p = (uint32_t)(par); uint32_t _d; \
    asm volatile("{\n\t.reg .pred p;\n\t" \
        "mbarrier.try_wait.parity.acquire.cta.shared::cta.b64 p, [%1], %2;\n\t" \
        "selp.b32 %0, 1, 0, p;\n\t}" : "=r"(_d) : "r"(_m), "r"(_p) : "memory"); \
    if (!_d) { \
        asm volatile("{\n\t.reg .pred P1;\n\tWL_%=:\n\t" \
            "mbarrier.try_wait.parity.acquire.cta.shared::cta.b64 P1, [%0], %1, 0x989680;\n\t" \
            "@P1 bra.uni WD_%=;\n\tbra.uni WL_%=;\n\tWD_%=:\n\t}" \
            :: "r"(_m), "r"(_p) : "memory"); \
    } } while (0)
#define TCGEN05_LD_32X32B_X32(r, tmem_addr) \
    asm volatile("tcgen05.ld.sync.aligned.32x32b.x32.b32 " \
        "{%0, %1, %2, %3, %4, %5, %6, %7, %8, %9, %10, %11, %12, %13, %14, %15, " \
        " %16, %17, %18, %19, %20, %21, %22, %23, %24, %25, %26, %27, %28, %29, %30, %31}, [%32];" \
        : "=r"((r)[0]),  "=r"((r)[1]),  "=r"((r)[2]),  "=r"((r)[3]), \
          "=r"((r)[4]),  "=r"((r)[5]),  "=r"((r)[6]),  "=r"((r)[7]), \
          "=r"((r)[8]),  "=r"((r)[9]),  "=r"((r)[10]), "=r"((r)[11]), \
          "=r"((r)[12]), "=r"((r)[13]), "=r"((r)[14]), "=r"((r)[15]), \
          "=r"((r)[16]), "=r"((r)[17]), "=r"((r)[18]), "=r"((r)[19]), \
          "=r"((r)[20]), "=r"((r)[21]), "=r"((r)[22]), "=r"((r)[23]), \
          "=r"((r)[24]), "=r"((r)[25]), "=r"((r)[26]), "=r"((r)[27]), \
          "=r"((r)[28]), "=r"((r)[29]), "=r"((r)[30]), "=r"((r)[31]) \
        : "r"(tmem_addr))

// SS-form cg1 kind::f16 MMA (bf16 inputs, fp32 accumulate in TMEM)
__device__ __forceinline__ void mma_f16_ss(uint32_t d_tmem, uint64_t a_desc,
                                           uint64_t b_desc, uint32_t idesc,
                                           uint32_t enable) {
    asm volatile("{\n\t.reg .pred p;\n\tsetp.ne.u32 p, %4, 0;\n\t"
                 "tcgen05.mma.cta_group::1.kind::f16 [%0], %1, %2, %3, {%5,%5,%5,%5}, p;\n\t}"
                 :: "r"(d_tmem), "l"(a_desc), "l"(b_desc), "r"(idesc),
                    "r"(enable), "r"(0u) : "memory");
}
// SW128 K-major descriptor (LBO=1, SBO=64, version=1, layout=SW128)
__device__ __forceinline__ uint64_t mk_desc(uint32_t addr) {
    return 0x4000404000010000ULL | ((uint64_t)(addr >> 4) & 0x3FFF);
}
#endif  // HAS_TCGEN05

// idesc: dtype=F32(1<<4) | atype=BF16(1<<7) | btype=BF16(1<<10) | (N/8)<<17 | (M/16)<<24
#define MMA_IDESC 0x08200490u

// packed f32x2 helpers for the fallback path (plain PTX, valid on compute_103)
__device__ __forceinline__ void fma2(unsigned long long& d,
                                     unsigned long long a,
                                     unsigned long long b) {
    asm("fma.rn.f32x2 %0, %1, %2, %0;" : "+l"(d) : "l"(a), "l"(b));
}
__device__ __forceinline__ unsigned long long splat2(float x) {
    unsigned long long r;
    asm("mov.b64 %0, {%1, %1};" : "=l"(r) : "f"(x));
    return r;
}

// ===========================================================================
// Kernel 1: fp32 -> (bf16 hi, bf16 lo residual) split
// ===========================================================================
__global__ void convert_k(const float* __restrict__ F) {
    int i = blockIdx.x * 256 + threadIdx.x;      // 4096*128 = 524288 elems
    float x = F[i];
    __nv_bfloat16 h = __float2bfloat16(x);
    g_Fhi[i] = h;
    g_Flo[i] = __float2bfloat16(x - __bfloat162float(h));
}

// ===========================================================================
// Kernel 2: S = F F^T. 128x128 tiles, triangular grid (528), mirror written
// from staged accumulators.
//   sm_103a-featured pass: tcgen05 bf16-split (hi*hi + hi*lo + lo*hi).
//   otherwise: proven f32x2 FFMA path (reads F directly).
// ===========================================================================
#define TILE_BYTES 32768                          // 128 rows x 256 B (bf16 K=128)
#define SM_A_HI 1024
#define SM_A_LO (SM_A_HI + TILE_BYTES)
#define SM_B_HI (SM_A_LO + TILE_BYTES)
#define SM_B_LO (SM_B_HI + TILE_BYTES)
#define SM_DYN  (SM_B_LO + TILE_BYTES)            // 132096 B dynamic smem
#define SM_ST_OFF 1024                            // staging reuses tile area after MMA

#if HAS_TCGEN05
__device__ __forceinline__ void load_tile_bf16(char* smem, int dst,
                                               const __nv_bfloat16* __restrict__ src,
                                               int rowBase, int tid) {
    // blocked-atom SW128 layout: atom = 8 rows x 64 bf16 (1024 B);
    // atom_offset = (row>>3) + (k>>6)*16  (16 atom-rows, 2 atom-cols)
#pragma unroll
    for (int c = tid; c < 2048; c += 256) {
        int row = c >> 4;
        int kc  = (c & 15) << 3;                 // bf16 col, multiple of 8
        uint4 v = *reinterpret_cast<const uint4*>(src + (size_t)(rowBase + row) * 128 + kc);
        uint32_t off = (uint32_t)(((row >> 3) + ((kc >> 6) << 4)) * 1024
                                  + (row & 7) * 128 + (kc & 63) * 2);
        off ^= (off >> 3) & 0x70;                // SW128 swizzle
        *reinterpret_cast<uint4*>(smem + dst + off) = v;
    }
}
#endif

__global__ __launch_bounds__(256, 1) void gemm_fused(const float* __restrict__ F) {
    extern __shared__ char smem[];
    const int tid = threadIdx.x;

    // triangular decode
    int lin = blockIdx.x, by = 0;
    while (lin >= 32 - by) { lin -= 32 - by; by++; }
    const int bx = by + lin;
    const int bi = by * 128, bj = bx * 128;

#if HAS_TCGEN05
    // ------------------- tensor-core path (sm_103a) -------------------
    const uint32_t sb = smem_u32(smem);
    const int wid = tid >> 5, lane = tid & 31;

    if (wid == 0) TCGEN05_ALLOC(sb + 0, 512);
    else          TCGEN05_RELINQUISH();
    if (tid == 0) MBARRIER_INIT(sb + 8, 1);

    load_tile_bf16(smem, SM_A_HI, g_Fhi, bi, tid);
    load_tile_bf16(smem, SM_A_LO, g_Flo, bi, tid);
    load_tile_bf16(smem, SM_B_HI, g_Fhi, bj, tid);
    load_tile_bf16(smem, SM_B_LO, g_Flo, bj, tid);
    __syncthreads();
    asm volatile("fence.proxy.async.shared::cta;" ::: "memory");

    uint32_t tmem_base;
    asm volatile("ld.shared.b32 %0, [%1];" : "=r"(tmem_base) : "r"(sb + 0));

    if (wid == 0 && elect_one_pred()) {
        const uint64_t dAhi = mk_desc(sb + SM_A_HI), dAlo = mk_desc(sb + SM_A_LO);
        const uint64_t dBhi = mk_desc(sb + SM_B_HI), dBlo = mk_desc(sb + SM_B_LO);
        // K-chunk offsets: 16 bf16 = 32 B = 2 units; atom_col 1 at 16 KB = 1024 units
        const uint32_t dk[8] = {0, 2, 4, 6, 1024, 1026, 1028, 1030};
        const uint64_t pa[3] = {dAhi, dAhi, dAlo};
        const uint64_t pb[3] = {dBhi, dBlo, dBhi};
#pragma unroll
        for (int p = 0; p < 3; p++)
#pragma unroll
            for (int k = 0; k < 8; k++)
                mma_f16_ss(tmem_base, pa[p] + dk[k], pb[p] + dk[k], MMA_IDESC,
                           (p > 0 || k > 0) ? 1u : 0u);
        TCGEN05_COMMIT(sb + 8);
    }

    __syncthreads();
    MBARRIER_WAIT_PARITY(sb + 8, 0);
    TCGEN05_FENCE_AFTER();

    // stage D (128x128 fp32) into col-major pad-133 smem
    float* st = reinterpret_cast<float*>(smem + SM_ST_OFF);
    if (wid < 4) {
        const int row = wid * 32 + lane;
#pragma unroll
        for (int q = 0; q < 4; q++) {
            uint32_t r[32];
            TCGEN05_LD_32X32B_X32(r, tmem_base + q * 32);
            TCGEN05_WAIT_LD();
            TCGEN05_FENCE_BEFORE();
#pragma unroll
            for (int c = 0; c < 32; c++)
                st[(q * 32 + c) * 133 + row] = __uint_as_float(r[c]);
        }
    }
    __syncthreads();

    {   // direct tile write
        const int c = tid & 127, rb = tid >> 7;
#pragma unroll
        for (int k = 0; k < 64; k++) {
            int r = rb + 2 * k;
            g_S[(size_t)(bi + r) * BSZ + bj + c] = st[c * 133 + r];
        }
    }
    if (bx != by) {                                // mirror (transposed) write
        const int r = tid & 127, cb = tid >> 7;
#pragma unroll
        for (int k = 0; k < 64; k++) {
            int c = cb + 2 * k;
            g_S[(size_t)(bj + c) * BSZ + bi + r] = st[c * 133 + r];
        }
    }

    __syncthreads();
    if (wid == 0) TCGEN05_DEALLOC(tmem_base, 512);
    (void)F;
#else
    // ------------------- fallback: f32x2 FFMA path (proven in R2) -------------------
    float* sh = reinterpret_cast<float*>(smem);   // As[16][132] | Bs[16][132]; reused
    float* As = sh;
    float* Bs = sh + 2112;

    const int tx = tid & 15, ty = tid >> 4;

    unsigned long long acc2[4][8];
#pragma unroll
    for (int p = 0; p < 4; p++)
#pragma unroll
        for (int c = 0; c < 8; c++) acc2[p][c] = 0ULL;

    const float4* F4 = reinterpret_cast<const float4*>(F);
    const int kq = tid & 3;
    const int lm = tid >> 2;

#pragma unroll 1
    for (int chunk = 0; chunk < 8; chunk++) {
        if (chunk) __syncthreads();
        float4 va0 = F4[(size_t)(bi + lm) * 32 + chunk * 4 + kq];
        float4 va1 = F4[(size_t)(bi + lm + 64) * 32 + chunk * 4 + kq];
        float4 vb0 = F4[(size_t)(bj + lm) * 32 + chunk * 4 + kq];
        float4 vb1 = F4[(size_t)(bj + lm + 64) * 32 + chunk * 4 + kq];
        {
            int kb = kq * 4;
            As[(kb + 0) * 132 + lm] = va0.x; As[(kb + 1) * 132 + lm] = va0.y;
            As[(kb + 2) * 132 + lm] = va0.z; As[(kb + 3) * 132 + lm] = va0.w;
            As[(kb + 0) * 132 + lm + 64] = va1.x; As[(kb + 1) * 132 + lm + 64] = va1.y;
            As[(kb + 2) * 132 + lm + 64] = va1.z; As[(kb + 3) * 132 + lm + 64] = va1.w;
            Bs[(kb + 0) * 132 + lm] = vb0.x; Bs[(kb + 1) * 132 + lm] = vb0.y;
            Bs[(kb + 2) * 132 + lm] = vb0.z; Bs[(kb + 3) * 132 + lm] = vb0.w;
            Bs[(kb + 0) * 132 + lm + 64] = vb1.x; Bs[(kb + 1) * 132 + lm + 64] = vb1.y;
            Bs[(kb + 2) * 132 + lm + 64] = vb1.z; Bs[(kb + 3) * 132 + lm + 64] = vb1.w;
        }
        __syncthreads();

        const float4* As4 = reinterpret_cast<const float4*>(As);
        const float4* Bs4 = reinterpret_cast<const float4*>(Bs);
#pragma unroll
        for (int k = 0; k < 16; k++) {
            float4 av0 = As4[k * 33 + ty];
            float4 av1 = As4[k * 33 + 16 + ty];
            float4 bv0 = Bs4[k * 33 + tx];
            float4 bv1 = Bs4[k * 33 + 16 + tx];
            unsigned long long A0 = reinterpret_cast<const ulonglong2*>(&av0)->x;
            unsigned long long A1 = reinterpret_cast<const ulonglong2*>(&av0)->y;
            unsigned long long A2 = reinterpret_cast<const ulonglong2*>(&av1)->x;
            unsigned long long A3 = reinterpret_cast<const ulonglong2*>(&av1)->y;
            unsigned long long B[8];
            B[0] = splat2(bv0.x); B[1] = splat2(bv0.y);
            B[2] = splat2(bv0.z); B[3] = splat2(bv0.w);
            B[4] = splat2(bv1.x); B[5] = splat2(bv1.y);
            B[6] = splat2(bv1.z); B[7] = splat2(bv1.w);
#pragma unroll
            for (int c = 0; c < 8; c++) {
                fma2(acc2[0][c], A0, B[c]);
                fma2(acc2[1][c], A1, B[c]);
                fma2(acc2[2][c], A2, B[c]);
                fma2(acc2[3][c], A3, B[c]);
            }
        }
    }

    auto accf = [&](int p, int c, int half) -> float {
        float2 f = *reinterpret_cast<float2*>(&acc2[p][c]);
        return half ? f.y : f.x;
    };
    auto rowOf = [&](int p, int h) -> int {
        return (p < 2) ? (ty * 4 + 2 * p + h) : (64 + ty * 4 + 2 * (p - 2) + h);
    };

#pragma unroll
    for (int p = 0; p < 4; p++)
#pragma unroll
        for (int h = 0; h < 2; h++) {
            int r = rowOf(p, h);
            float4 w0 = make_float4(accf(p, 0, h), accf(p, 1, h), accf(p, 2, h), accf(p, 3, h));
            float4 w1 = make_float4(accf(p, 4, h), accf(p, 5, h), accf(p, 6, h), accf(p, 7, h));
            *reinterpret_cast<float4*>(&g_S[(size_t)(bi + r) * BSZ + bj + tx * 4]) = w0;
            *reinterpret_cast<float4*>(&g_S[(size_t)(bi + r) * BSZ + bj + 64 + tx * 4]) = w1;
        }

    if (bx != by) {
#pragma unroll 1
        for (int q = 0; q < 4; q++) {
            __syncthreads();
            int cbase = (q < 2) ? (tx * 4 - 32 * q) : (64 + tx * 4 - 32 * q);
            if (cbase >= 0 && cbase < 32) {
                int coff = (q < 2) ? 0 : 4;
#pragma unroll
                for (int j = 0; j < 4; j++)
#pragma unroll
                    for (int p = 0; p < 4; p++) {
                        sh[(cbase + j) * 132 + rowOf(p, 0)] = accf(p, coff + j, 0);
                        sh[(cbase + j) * 132 + rowOf(p, 1)] = accf(p, coff + j, 1);
                    }
            }
            __syncthreads();
            int cl = tid >> 3, f = tid & 7;
#pragma unroll
            for (int kk = 0; kk < 4; kk++) {
                int f4 = f + kk * 8;
                float4 v = *reinterpret_cast<const float4*>(&sh[cl * 132 + f4 * 4]);
                *reinterpret_cast<float4*>(
                    &g_S[(size_t)(bj + q * 32 + cl) * BSZ + bi + f4 * 4]) = v;
            }
        }
    }
#endif
}

// ===========================================================================
// Kernel 3: per-row pass. Fixed-threshold bracket (counts fused into pass 1),
// exact tie-aware rank on candidates. Bisection fallback keeps it exact.
// ===========================================================================
__global__ __launch_bounds__(256) void row_kernel(const int* __restrict__ labels) {
    __shared__ int   s_i[8][8];
    __shared__ float s_f[8][4];
    __shared__ unsigned scnt[8][8];
    __shared__ unsigned scounts[8];
    __shared__ float cand[2048];
    __shared__ unsigned ccount;
    __shared__ float sT;
    __shared__ unsigned sgt;

    const int i = blockIdx.x, tid = threadIdx.x;
    const int lane = tid & 31, warp = tid >> 5;
    const int myLab = labels[i];

    const float4* S4 = reinterpret_cast<const float4*>(g_S + (size_t)i * BSZ);
    const int4*   L4 = reinterpret_cast<const int4*>(labels);

    float v[16];
    unsigned negm = 0;
#pragma unroll
    for (int q = 0; q < 4; q++) {
        int idx = tid + q * 256;
        float4 x = S4[idx];
        int4   l = L4[idx];
        v[q * 4 + 0] = x.x; v[q * 4 + 1] = x.y; v[q * 4 + 2] = x.z; v[q * 4 + 3] = x.w;
        if (l.x != myLab) negm |= 1u << (q * 4 + 0);
        if (l.y != myLab) negm |= 1u << (q * 4 + 1);
        if (l.z != myLab) negm |= 1u << (q * 4 + 2);
        if (l.w != myLab) negm |= 1u << (q * 4 + 3);
    }

    // ---- pass 1: max + threshold counts + positive sums (one loop) ----
    const float T1 = 0.10f, T2 = 0.13f, T3 = 0.16f, T4 = 0.19f;
    float mloc = -1e30f, psum = 0.0f, pcnt = 0.0f;
    int tc1 = 0, tc2 = 0, tc3 = 0, tc4 = 0;
    int pc1 = 0, pc2 = 0, pc3 = 0, pc4 = 0;
#pragma unroll
    for (int e = 0; e < 16; e++) {
        float x = v[e];
        mloc = fmaxf(mloc, x);
        tc1 += x > T1; tc2 += x > T2; tc3 += x > T3; tc4 += x > T4;
        if (!((negm >> e) & 1u)) {
            int j = (tid + (e >> 2) * 256) * 4 + (e & 3);
            if (j != i) {
                psum += x; pcnt += 1.0f;
                pc1 += x > T1; pc2 += x > T2; pc3 += x > T3; pc4 += x > T4;
            }
        }
    }
#pragma unroll
    for (int o = 16; o; o >>= 1) {
        mloc = fmaxf(mloc, __shfl_xor_sync(0xFFFFFFFFu, mloc, o));
        psum += __shfl_xor_sync(0xFFFFFFFFu, psum, o);
        pcnt += __shfl_xor_sync(0xFFFFFFFFu, pcnt, o);
    }
    tc1 = __reduce_add_sync(0xFFFFFFFFu, tc1); tc2 = __reduce_add_sync(0xFFFFFFFFu, tc2);
    tc3 = __reduce_add_sync(0xFFFFFFFFu, tc3); tc4 = __reduce_add_sync(0xFFFFFFFFu, tc4);
    pc1 = __reduce_add_sync(0xFFFFFFFFu, pc1); pc2 = __reduce_add_sync(0xFFFFFFFFu, pc2);
    pc3 = __reduce_add_sync(0xFFFFFFFFu, pc3); pc4 = __reduce_add_sync(0xFFFFFFFFu, pc4);
    if (lane == 0) {
        s_i[warp][0] = tc1; s_i[warp][1] = tc2; s_i[warp][2] = tc3; s_i[warp][3] = tc4;
        s_i[warp][4] = pc1; s_i[warp][5] = pc2; s_i[warp][6] = pc3; s_i[warp][7] = pc4;
        s_f[warp][0] = mloc; s_f[warp][1] = psum; s_f[warp][2] = pcnt;
    }
    __syncthreads();
    float m = s_f[0][0]; psum = s_f[0][1]; pcnt = s_f[0][2];
    int cN1 = s_i[0][0] - s_i[0][4], cN2 = s_i[0][1] - s_i[0][5];
    int cN3 = s_i[0][2] - s_i[0][6], cN4 = s_i[0][3] - s_i[0][7];
#pragma unroll
    for (int w = 1; w < 8; w++) {
        m = fmaxf(m, s_f[w][0]); psum += s_f[w][1]; pcnt += s_f[w][2];
        cN1 += s_i[w][0] - s_i[w][4]; cN2 += s_i[w][1] - s_i[w][5];
        cN3 += s_i[w][2] - s_i[w][6]; cN4 += s_i[w][3] - s_i[w][7];
    }
    cN1 -= 1; cN2 -= 1; cN3 -= 1; cN4 -= 1;      // exclude self (s==1 above all thresholds)
    const int cnt = (int)pcnt;
    const int negcnt = BSZ - 1 - cnt;
    const float lsum = 10.0f * psum - 10.0f * pcnt * m;

    float nsum = 0.0f, esum = 0.0f, tail = 0.0f;

    if (negcnt <= KSEL) {
#pragma unroll
        for (int e = 0; e < 16; e++) {
            int j = (tid + (e >> 2) * 256) * 4 + (e & 3);
            float lg = (v[e] - m) * 10.0f;
            if ((negm >> e) & 1u)      nsum += __expf(lg);
            else if (j != i)           esum += __expf(lg);
        }
#pragma unroll
        for (int o = 16; o; o >>= 1) {
            nsum += __shfl_xor_sync(0xFFFFFFFFu, nsum, o);
            esum += __shfl_xor_sync(0xFFFFFFFFu, esum, o);
        }
        __syncthreads();
        if (lane == 0) { s_f[warp][0] = nsum; s_f[warp][1] = esum; }
        __syncthreads();
        nsum = 0.0f; esum = 0.0f;
#pragma unroll
        for (int w = 0; w < 8; w++) { nsum += s_f[w][0]; esum += s_f[w][1]; }
    } else {
        // ---- determine bracket (lo, hi], cntAbove = #neg > hi ----
        float lo = 0.0f, hi = 0.0f; int cntAbove = 0; bool fast = false;
        {
            const float tj[5] = {-2.0f, T1, T2, T3, T4};
            const int   cN[5] = {negcnt, cN1, cN2, cN3, cN4};
            int js = -1;
#pragma unroll
            for (int j = 4; j >= 1; j--) if (cN[j] < KSEL) js = j;
            if (js >= 2) {
                int gap = cN[js - 1] - cN[js];
                if (gap >= 1 && gap <= 2048) {
                    lo = tj[js - 1]; hi = tj[js]; cntAbove = cN[js]; fast = true;
                }
            }
        }
        if (!fast) {
            // fallback: 9-ary bisection (exact for any data)
            float blo = -1.01f, bhi = 1.01f;
            int cLo = negcnt, cHi = 0;
            for (int round = 0; round < 8 && (cLo - cHi) > 48; round++) {
                float w9 = (bhi - blo) * (1.0f / 9.0f);
                float t[8];
#pragma unroll
                for (int j = 0; j < 8; j++) t[j] = blo + w9 * (float)(j + 1);
                unsigned c[8] = {0,0,0,0,0,0,0,0};
#pragma unroll
                for (int e = 0; e < 16; e++)
                    if ((negm >> e) & 1u) {
                        float x = v[e];
#pragma unroll
                        for (int j = 0; j < 8; j++) c[j] += (x > t[j]);
                    }
#pragma unroll
                for (int j = 0; j < 8; j++) c[j] = __reduce_add_sync(0xFFFFFFFFu, c[j]);
                if (lane == 0)
#pragma unroll
                    for (int j = 0; j < 8; j++) scnt[warp][j] = c[j];
                __syncthreads();
                if (tid < 8) {
                    unsigned s = 0;
#pragma unroll
                    for (int wq = 0; wq < 8; wq++) s += scnt[wq][tid];
                    scounts[tid] = s;
                }
                __syncthreads();
                int jstar = 8;
#pragma unroll
                for (int j = 7; j >= 0; j--) if ((int)scounts[j] < KSEL) jstar = j;
                if (jstar == 8)      { blo = t[7]; cLo = (int)scounts[7]; }
                else if (jstar == 0) { bhi = t[0]; cHi = (int)scounts[0]; }
                else { blo = t[jstar - 1]; cLo = (int)scounts[jstar - 1];
                       bhi = t[jstar];     cHi = (int)scounts[jstar]; }
                __syncthreads();
            }
            lo = blo; hi = bhi; cntAbove = cHi;
        }

        // ---- pass 2: exp sums + candidate gather ----
        if (tid == 0) ccount = 0;
        __syncthreads();
#pragma unroll
        for (int e = 0; e < 16; e++) {
            float x = v[e];
            if ((negm >> e) & 1u) {
                if (x > hi) nsum += __expf((x - m) * 10.0f);
                else if (x > lo) {
                    unsigned u = atomicAdd(&ccount, 1u);
                    if (u < 2048) cand[u] = x;
                }
            } else {
                int j = (tid + (e >> 2) * 256) * 4 + (e & 3);
                if (j != i) esum += __expf((x - m) * 10.0f);
            }
        }
        __syncthreads();
        const int c = (int)min(ccount, 2048u);

        // ---- exact tie-aware rank among candidates ----
        for (int t = tid; t < c; t += 256) {
            float x = cand[t];
            int gt = 0, eq = 0;
            for (int u = 0; u < c; u++) {
                float y = cand[u];
                gt += (y > x); eq += (y == x);
            }
            if (cntAbove + gt < KSEL && KSEL <= cntAbove + gt + eq) {
                sT = x; sgt = (unsigned)(cntAbove + gt);
            }
        }
        __syncthreads();
        const float T = sT;
        const int ties = KSEL - (int)sgt;
        for (int t = tid; t < c; t += 256)
            if (cand[t] > T) nsum += __expf((cand[t] - m) * 10.0f);
        tail = (float)ties * __expf((T - m) * 10.0f);

#pragma unroll
        for (int o = 16; o; o >>= 1) {
            nsum += __shfl_xor_sync(0xFFFFFFFFu, nsum, o);
            esum += __shfl_xor_sync(0xFFFFFFFFu, esum, o);
        }
        __syncthreads();
        if (lane == 0) { s_f[warp][0] = nsum; s_f[warp][1] = esum; }
        __syncthreads();
        nsum = 0.0f; esum = 0.0f;
#pragma unroll
        for (int w = 0; w < 8; w++) { nsum += s_f[w][0]; esum += s_f[w][1]; }
    }

    if (tid == 0) {
        float denom = esum + nsum + tail;
        bool valid = (myLab > 0) && (cnt > 0);
        float mlpp = (cnt > 0) ? (lsum / pcnt) : 0.0f;
        g_perrow[i] = valid ? (-2.0f * (mlpp - logf(denom))) : 0.0f;
        g_validf[i] = valid ? 1.0f : 0.0f;
    }
}

// ===========================================================================
// Kernel 4: deterministic final reduction
// ===========================================================================
__global__ void finalize(float* __restrict__ out) {
    __shared__ float sp[256], sv[256];
    int tid = threadIdx.x;
    float ps = 0.0f, vs = 0.0f;
    for (int j = tid; j < BSZ; j += 256) { ps += g_perrow[j]; vs += g_validf[j]; }
    sp[tid] = ps; sv[tid] = vs;
    __syncthreads();
#pragma unroll
    for (int o = 128; o; o >>= 1) {
        if (tid < o) { sp[tid] += sp[tid + o]; sv[tid] += sv[tid + o]; }
        __syncthreads();
    }
    if (tid == 0) out[0] = sp[0] / sv[0];
}

// ===========================================================================
extern "C" void kernel_launch(void* const* d_in, const int* in_sizes, int n_in,
                              void* d_out, int out_size) {
    (void)in_sizes; (void)n_in; (void)out_size;
    const float* F      = (const float*)d_in[0];
    const int*   labels = (const int*)d_in[1];
    float*       out    = (float*)d_out;

    static int smem_set = 0;
    if (!smem_set) {
        cudaFuncSetAttribute(gemm_fused, cudaFuncAttributeMaxDynamicSharedMemorySize, SM_DYN);
        smem_set = 1;
    }

    convert_k<<<BSZ * 128 / 256, 256>>>(F);
    gemm_fused<<<528, 256, SM_DYN>>>(F);
    row_kernel<<<BSZ, 256>>>(labels);
    finalize<<<1, 256>>>(out);
}